// round 3
// baseline (speedup 1.0000x reference)
#include <cuda_runtime.h>

#define NN 1024
#define DD 256
#define DK 32

// scratch: normalized mu and sigma^2 = exp(log_sigma)
__device__ float g_mu[NN * DD];
__device__ float g_s[NN * DD];

__device__ __forceinline__ float frcp(float x) {
    float r; asm("rcp.approx.ftz.f32 %0, %1;" : "=f"(r) : "f"(x)); return r;
}
__device__ __forceinline__ float flg2(float x) {
    float r; asm("lg2.approx.ftz.f32 %0, %1;" : "=f"(r) : "f"(x)); return r;
}

// One block per row: normalize mu_X row (F.normalize, eps=1e-12) and exp(log_sigma).
__global__ void prep_kernel(const float* __restrict__ muX,
                            const float* __restrict__ logsig) {
    const int row = blockIdx.x;
    const int t = threadIdx.x;  // 256 threads == DD
    float x = muX[row * DD + t];
    float v = x * x;
    #pragma unroll
    for (int o = 16; o; o >>= 1) v += __shfl_xor_sync(0xffffffffu, v, o);
    __shared__ float red[8];
    __shared__ float inv_sh;
    if ((t & 31) == 0) red[t >> 5] = v;
    __syncthreads();
    if (t == 0) {
        float tot = 0.f;
        #pragma unroll
        for (int k = 0; k < 8; k++) tot += red[k];
        float nrm = sqrtf(tot);
        inv_sh = 1.0f / fmaxf(nrm, 1e-12f);
    }
    __syncthreads();
    g_mu[row * DD + t] = x * inv_sh;
    g_s[row * DD + t] = expf(logsig[row * DD + t]);
}

// 32x32 output tile per block; only upper-triangular tiles (tj >= ti) do work,
// mirroring into the lower triangle. 256 threads: tx = j-in-tile, wy = i-group,
// each thread accumulates 4 outputs (i = wy, wy+8, wy+16, wy+24).
__global__ __launch_bounds__(256) void pair_kernel(float* __restrict__ out) {
    const int ti = blockIdx.y, tj = blockIdx.x;
    if (tj < ti) return;

    // [d][row] layout, padded to 33 so loads (lane=d, stride 33) and
    // compute reads (lane=row, stride 1) are both bank-conflict-free.
    __shared__ float smui[DK][33];
    __shared__ float ssi [DK][33];
    __shared__ float smuj[DK][33];
    __shared__ float ssj [DK][33];

    const int t = threadIdx.x;
    const int tx = t & 31;   // j within tile
    const int wy = t >> 5;   // 0..7
    const int i0 = ti * 32, j0 = tj * 32;

    float acc[4] = {0.f, 0.f, 0.f, 0.f};

    for (int dc = 0; dc < DD; dc += DK) {
        __syncthreads();  // previous chunk's compute done before overwrite
        #pragma unroll
        for (int p = 0; p < 4; p++) {
            int r = wy + 8 * p;
            smui[tx][r] = g_mu[(i0 + r) * DD + dc + tx];
            ssi [tx][r] = g_s [(i0 + r) * DD + dc + tx];
            smuj[tx][r] = g_mu[(j0 + r) * DD + dc + tx];
            ssj [tx][r] = g_s [(j0 + r) * DD + dc + tx];
        }
        __syncthreads();

        #pragma unroll 8
        for (int d = 0; d < DK; d++) {
            float mj = smuj[d][tx];
            float sj = ssj[d][tx];
            #pragma unroll
            for (int k = 0; k < 4; k++) {
                float mi = smui[d][wy + 8 * k];   // broadcast across warp
                float si = ssi [d][wy + 8 * k];
                float ssum = si + sj;
                float diff = mi - mj;
                // term = diff^2 / ssum + ln(ssum)   (eps=1e-10 negligible: ssum >= ~0.02)
                acc[k] = fmaf(diff * diff, frcp(ssum), acc[k]);
                acc[k] = fmaf(flg2(ssum), 0.6931471805599453f, acc[k]);
            }
        }
    }

    #pragma unroll
    for (int k = 0; k < 4; k++) {
        int i = i0 + wy + 8 * k;
        float v = -acc[k];
        out[i * NN + (j0 + tx)] = v;               // coalesced
        if (ti != tj)
            out[(j0 + tx) * NN + i] = v;           // mirrored (scattered, cheap)
    }
}

extern "C" void kernel_launch(void* const* d_in, const int* in_sizes, int n_in,
                              void* d_out, int out_size) {
    const float* muX  = (const float*)d_in[0];
    const float* lsig = (const float*)d_in[1];
    float* out = (float*)d_out;

    prep_kernel<<<NN, DD>>>(muX, lsig);

    dim3 grid(NN / 32, NN / 32);   // lower-triangle blocks exit immediately
    pair_kernel<<<grid, 256>>>(out);
}